// round 3
// baseline (speedup 1.0000x reference)
#include <cuda_runtime.h>

#define NODES_MAX 100000
#define D 64

// Scratch accumulators (device globals: no runtime allocation allowed).
__device__ float g_sum[(size_t)NODES_MAX * D];
__device__ int   g_deg[NODES_MAX];

// ---------------------------------------------------------------------------
// Kernel 1: zero the accumulators (graph replays require re-zeroing each call)
// ---------------------------------------------------------------------------
__global__ void zero_kernel(int n_nodes) {
    int tid = blockIdx.x * blockDim.x + threadIdx.x;
    int stride = gridDim.x * blockDim.x;
    int total4 = n_nodes * (D / 4);
    float4 z = make_float4(0.f, 0.f, 0.f, 0.f);
    for (int i = tid; i < total4; i += stride)
        ((float4*)g_sum)[i] = z;
    for (int i = tid; i < n_nodes; i += stride)
        g_deg[i] = 0;
}

// ---------------------------------------------------------------------------
// Kernel 2: edge scatter. 16 threads per edge; each loads one float4 of
// h[src] and does a vectorized f32x4 reduction into g_sum[dst].
// ---------------------------------------------------------------------------
__global__ void edge_kernel(const float* __restrict__ h,
                            const int* __restrict__ src,
                            const int* __restrict__ dst, int nE) {
    int t = blockIdx.x * blockDim.x + threadIdx.x;
    int e = t >> 4;
    int lane = t & 15;
    if (e >= nE) return;
    int s = __ldg(src + e);
    int d = __ldg(dst + e);
    float4 v = __ldg(((const float4*)h) + (size_t)s * (D / 4) + lane);
    float* p = g_sum + (size_t)d * D + lane * 4;
    unsigned long long gp = (unsigned long long)__cvta_generic_to_global(p);
    asm volatile("red.global.add.v4.f32 [%0], {%1,%2,%3,%4};"
                 :: "l"(gp), "f"(v.x), "f"(v.y), "f"(v.z), "f"(v.w)
                 : "memory");
    if (lane == 0) atomicAdd(&g_deg[d], 1);
}

// ---------------------------------------------------------------------------
// Kernel 3: per-node update. 256 threads/block = 2 nodes x 64 outputs x 2
// k-halves. Each thread keeps its 64 W coefficients in registers for the
// whole (grid-stride) node loop; inputs broadcast via shared memory.
// ---------------------------------------------------------------------------
__global__ __launch_bounds__(256) void update_kernel(
    const float* __restrict__ h, const float* __restrict__ W,
    const float* __restrict__ b, float* __restrict__ out, int n) {
    int tid  = threadIdx.x;
    int j    = tid & 63;          // output index
    int s    = (tid >> 6) & 1;    // 0 -> h half, 1 -> c half
    int slot = tid >> 7;          // node slot within block (0/1)

    // W[j][s*64 + k], k = 0..63, kept in registers across all nodes.
    float4 w[16];
#pragma unroll
    for (int q = 0; q < 16; q++)
        w[q] = __ldg((const float4*)(W + j * 128 + s * 64) + q);
    float bj = __ldg(b + j);

    __shared__ float sh_x[2][2][D];    // [slot][0=h row,1=c row][k]
    __shared__ float sh_part[2][D];    // c-half partial sums
    __shared__ float sh_red[8];        // per-warp sum-of-squares
    __shared__ int   sh_degpos[2];

    for (int base = blockIdx.x * 2; base < n; base += gridDim.x * 2) {
        int node = base + slot;
        bool active = node < n;
        __syncthreads();  // protect shared reuse across iterations
        if (active) {
            if (s == 0) {
                sh_x[slot][0][j] = __ldg(h + (size_t)node * D + j);
            } else {
                int dg = g_deg[node];
                float inv = 1.0f / (float)max(dg, 1);
                sh_x[slot][1][j] = g_sum[(size_t)node * D + j] * inv;
                if (j == 0) sh_degpos[slot] = (dg > 0);
            }
        }
        __syncthreads();

        float acc = 0.f;
        const float* x = sh_x[slot][s];
#pragma unroll
        for (int q = 0; q < 16; q++) {
            float4 xv = *(const float4*)(x + 4 * q);
            acc = fmaf(xv.x, w[q].x, acc);
            acc = fmaf(xv.y, w[q].y, acc);
            acc = fmaf(xv.z, w[q].z, acc);
            acc = fmaf(xv.w, w[q].w, acc);
        }
        if (s == 1) sh_part[slot][j] = acc;
        __syncthreads();

        float bundle = 0.f;
        if (s == 0) {
            bundle = acc + sh_part[slot][j] + bj;
            float sq = bundle * bundle;
#pragma unroll
            for (int off = 16; off; off >>= 1)
                sq += __shfl_xor_sync(0xffffffffu, sq, off);
            if ((tid & 31) == 0) sh_red[tid >> 5] = sq;
        }
        __syncthreads();
        if (s == 0 && active) {
            int wbase = slot * 4;  // slot0 -> warps {0,1}, slot1 -> warps {4,5}
            float sumsq = sh_red[wbase] + sh_red[wbase + 1];
            float nrm = sqrtf(sumsq);
            float inv = 1.0f / fmaxf(nrm, 1e-12f);
            float nh = fmaxf(bundle * inv, 0.f);
            float hv = sh_x[slot][0][j];
            float upd = sh_degpos[slot] ? nh : hv;
            out[(size_t)node * D + j] = hv + upd;
        }
    }
}

// ---------------------------------------------------------------------------
// Launch: inputs per metadata order: h[N*64] f32, W[64*128] f32, b[64] f32,
// src[E] i32, dst[E] i32. Output: f32 [N*64].
// ---------------------------------------------------------------------------
extern "C" void kernel_launch(void* const* d_in, const int* in_sizes, int n_in,
                              void* d_out, int out_size) {
    const float* h  = (const float*)d_in[0];
    const float* W  = (const float*)d_in[1];
    const float* b  = (const float*)d_in[2];
    const int* src  = (const int*)d_in[3];
    const int* dst  = (const int*)d_in[4];
    float* out = (float*)d_out;

    int n  = in_sizes[0] / D;
    int nE = in_sizes[3];

    zero_kernel<<<2048, 256>>>(n);

    long long et = (long long)nE * 16;
    int eb = (int)((et + 255) / 256);
    edge_kernel<<<eb, 256>>>(h, src, dst, nE);

    update_kernel<<<1184, 256>>>(h, W, b, out, n);
}